// round 13
// baseline (speedup 1.0000x reference)
#include <cuda_runtime.h>
#include <float.h>

#define KMAX   256
#define BMAX   8
#define BINS   4096                 // guide bins; 16 sub-bins each -> 65536 sub-bins
#define SUBS   65536
#define GBLK   16                   // guide build blocks (4096 / 256)
#define GRIDX  152                  // 152 x 8 = 1216 CTAs = 8/SM on 152 SMs

// Exact segment-index machinery:
//   t(x) = clamp((int)(x*65536f), 0, 65535)  -- exact: *2^16 only shifts exponent
//   g_guide[j] = (cnt << 16) | mask16 : cnt = #knots with t(E) < j*16,
//                mask bit i set iff some knot has t(E) == j*16+i
// Per batch: y = slope[s]*x + offset[s], s = #{k : E[k] <= x}
//   (s=0 low clamp, s=K high clamp); offsets built in double (no cancellation).
__device__ unsigned g_guide[BINS];
__device__ float2   g_seg2[BMAX][KMAX + 2];

// ---------------------------------------------------------------------------
// Kernel 1 (merged setup). Grid = B + GBLK, 256 threads.
// ---------------------------------------------------------------------------
__global__ void setup_tables(const float* __restrict__ w,    // [B, NB]
                             const float* __restrict__ E,    // [K]
                             const float* __restrict__ f0,   // [K]
                             const float* __restrict__ Hb,   // [K, NB]
                             int K, int NB, int B)
{
    const int blk = blockIdx.x;
    const int tid = threadIdx.x;

    if (blk < B) {
        const int b = blk;
        __shared__ float c[KMAX];
        __shared__ float Es[KMAX];

        if (tid < K) {
            float acc = f0[tid];
            const float* hrow = Hb + (long long)tid * NB;
            const float* wrow = w  + (long long)b   * NB;
            #pragma unroll 5
            for (int n = 0; n < NB; n++)
                acc = fmaf(hrow[n], wrow[n], acc);
            c[tid]  = acc;
            Es[tid] = E[tid];
        }
        __syncthreads();

        if (tid == 0) {
            g_seg2[b][0] = make_float2(0.0f, c[0]);       // x <  E[0]
            g_seg2[b][K] = make_float2(0.0f, c[K - 1]);   // x >= E[K-1]
        }
        if (tid >= 1 && tid <= K - 1) {
            const double e0 = (double)Es[tid - 1], e1 = (double)Es[tid];
            const double sl = ((double)c[tid] - (double)c[tid - 1]) / (e1 - e0);
            const double of = (double)c[tid - 1] - sl * e0;
            g_seg2[b][tid] = make_float2((float)sl, (float)of);
        }
    } else {
        __shared__ int tE[KMAX];
        for (int k = tid; k < K; k += 256) {
            int t = (int)(E[k] * 65536.0f);               // exact
            tE[k] = min(max(t, 0), SUBS - 1);
        }
        __syncthreads();

        const int j = (blk - B) * 256 + tid;
        if (j < BINS) {
            const int lo = j * 16, hi = lo + 16;
            int cnt = 0; unsigned mask = 0u;
            for (int k = 0; k < K; k++) {
                const int t = tE[k];
                cnt += (t < lo);
                if (t >= lo && t < hi) mask |= 1u << (t - lo);
            }
            g_guide[j] = ((unsigned)cnt << 16) | mask;
        }
    }
}

// ---------------------------------------------------------------------------
// Kernel 2: streaming apply. Grid = (GRIDX, B), 256 threads.
// Hot path is fully branchless: guide LDS.32 + <=2 predicated correction
// LDS.32 (broadcast when inactive) + seg LDS.64 + FMA.
// ---------------------------------------------------------------------------
__device__ __forceinline__ float interp1(float x,
                                         const unsigned* __restrict__ G,
                                         const float2*   __restrict__ S,
                                         const float*    __restrict__ Ek)
{
    int t = (int)(x * 65536.0f);                          // exact floor for x>=0
    t = min(max(t, 0), SUBS - 1);
    const unsigned e = G[t >> 4];                         // LDS.32, ~3.4 waves
    const int ts = t & 15;
    const unsigned m = e & 0xFFFFu;
    int s = (int)(e >> 16) + __popc(m & ((1u << ts) - 1u));
    const int hit = (int)((m >> ts) & 1u);                // knot shares x's sub-bin (~0.4%/lane)
    // Branchless correction: count knots inside x's sub-bin with E <= x.
    // Inactive lanes read Ek[0] (broadcast). Knots past the sub-bin have E > x
    // automatically; Ek is +inf padded so s never overruns. Two steps cover
    // any realistic multiplicity (>=3 knots per 2^-16 sub-bin ~ nonexistent).
    {
        const float e1 = Ek[hit ? s : 0];
        s += hit & (e1 <= x);
        const float e2 = Ek[hit ? s : 0];
        s += hit & (e2 <= x);
    }
    const float2 so = S[s];                               // LDS.64, ~6.4 waves
    return __saturatef(fmaf(x, so.x, so.y));
}

__global__ void __launch_bounds__(256, 8)
tmo_apply(const float* __restrict__ img, float* __restrict__ out,
          const float* __restrict__ E, int npix, int K)
{
    __shared__ unsigned G_s[BINS];        // 16 KB
    __shared__ float2   S_s[KMAX + 2];    //  ~2 KB
    __shared__ float    E_s[KMAX + 2];    //  ~1 KB (+inf padded)

    const int b   = blockIdx.y;
    const int tid = threadIdx.x;

    for (int i = tid; i < BINS; i += 256) G_s[i] = g_guide[i];
    {
        const float2* s = &g_seg2[b][0];
        for (int i = tid; i <= K; i += 256) S_s[i] = s[i];
        for (int i = tid; i < K;  i += 256) E_s[i] = E[i];
        if (tid == 0) { E_s[K] = FLT_MAX; E_s[K + 1] = FLT_MAX; }
    }
    __syncthreads();

    const long long base = (long long)b * (long long)npix;
    const float4* __restrict__ in4  = (const float4*)(img + base);
    float4*       __restrict__ out4 = (float4*)(out + base);

    const int n4     = npix >> 2;
    const int stride = GRIDX * 256;
    int i = blockIdx.x * 256 + tid;

    // 4x unrolled (R6-proven shape at 64 warps/SM)
    for (; i + 3 * stride < n4; i += 4 * stride) {
        float4 xa[4];
        #pragma unroll
        for (int u = 0; u < 4; u++) xa[u] = in4[i + u * stride];
        #pragma unroll
        for (int u = 0; u < 4; u++) {
            float4 y;
            y.x = interp1(xa[u].x, G_s, S_s, E_s);
            y.y = interp1(xa[u].y, G_s, S_s, E_s);
            y.z = interp1(xa[u].z, G_s, S_s, E_s);
            y.w = interp1(xa[u].w, G_s, S_s, E_s);
            out4[i + u * stride] = y;
        }
    }
    for (; i < n4; i += stride) {
        const float4 x = in4[i];
        float4 y;
        y.x = interp1(x.x, G_s, S_s, E_s);
        y.y = interp1(x.y, G_s, S_s, E_s);
        y.z = interp1(x.z, G_s, S_s, E_s);
        y.w = interp1(x.w, G_s, S_s, E_s);
        out4[i] = y;
    }

    // scalar tail (npix not divisible by 4; empty for this shape)
    if (blockIdx.x == 0) {
        for (int tix = (n4 << 2) + tid; tix < npix; tix += 256)
            out[base + tix] = interp1(img[base + tix], G_s, S_s, E_s);
    }
}

// ---------------------------------------------------------------------------
// Inputs (metadata order): hdr_image [B,C,H,W] f32, weights_w [B,NB] f32,
//                          E_samples [K] f32, f0_mean [K] f32, H_basis [K,NB] f32
// Output: [B,C,H,W] f32
// ---------------------------------------------------------------------------
extern "C" void kernel_launch(void* const* d_in, const int* in_sizes, int n_in,
                              void* d_out, int out_size)
{
    const float* img = (const float*)d_in[0];
    const float* w   = (const float*)d_in[1];
    const float* E   = (const float*)d_in[2];
    const float* f0  = (const float*)d_in[3];
    const float* Hb  = (const float*)d_in[4];
    float* out = (float*)d_out;

    const int K    = in_sizes[2];                 // 256
    const int NB   = in_sizes[4] / K;             // 25
    const int B    = in_sizes[1] / NB;            // 8
    const int npix = in_sizes[0] / B;             // C*H*W = 6,220,800

    setup_tables<<<B + GBLK, 256>>>(w, E, f0, Hb, K, NB, B);

    dim3 grid(GRIDX, B);                          // 1216 CTAs = 8/SM
    tmo_apply<<<grid, 256>>>(img, out, E, npix, K);
}